// round 5
// baseline (speedup 1.0000x reference)
#include <cuda_runtime.h>
#include <math.h>

typedef unsigned long long ull;

#define Bv 32
#define Lv 1024
#define Hv 512
#define NGROUP 8
#define CPG 16
#define ROWP 516   // padded row stride (floats) in smem: 516 mod 32 = 4 -> conflict-free

// ---------------- device scratch (no cudaMalloc allowed) ----------------
__device__ float g_pre[(size_t)Lv * Bv * 1536];   // [t][b][0..1023]=x_ru+b_ru, [1024..1535]=x_c+b_c
__device__ float g_h [Bv * Hv];                   // h[b][j] (step exchange)
__device__ float g_rh[Bv * Hv];                   // (r*h)[b][j]
__device__ float g_z [Bv * Hv];                   // z[b][n]
__device__ unsigned int g_flag[NGROUP * CPG];     // zero-init; monotonic across replays

// ---------------- f32x2 helpers ----------------
__device__ __forceinline__ ull splat2(float x) {
    ull r; asm("mov.b64 %0, {%1, %1};" : "=l"(r) : "f"(x)); return r;
}
__device__ __forceinline__ float2 unpack2(ull v) {
    float2 f; asm("mov.b64 {%0, %1}, %2;" : "=f"(f.x), "=f"(f.y) : "l"(v)); return f;
}
__device__ __forceinline__ void ffma2(ull& d, ull a, ull b) {
    asm("fma.rn.f32x2 %0, %1, %2, %0;" : "+l"(d) : "l"(a), "l"(b));
}

__device__ __forceinline__ float fast_sigmoid(float x) {
    x = fminf(fmaxf(x, -30.0f), 30.0f);
    return 1.0f / (1.0f + __expf(-x));
}
__device__ __forceinline__ float fast_tanh(float x) {
    x = fminf(fmaxf(x, -15.0f), 15.0f);
    float e = __expf(2.0f * x);
    return (e - 1.0f) / (e + 1.0f);
}

// 16 floats of w x 16 floats of h -> 8 FFMA2 into 8 rotating accumulators.
// Plain C++ LDS.128 loads: ptxas is free to software-pipeline them.
__device__ __forceinline__ void dot16(const ulonglong2* __restrict__ wp,
                                      const ulonglong2* __restrict__ hp,
                                      int k, ull* acc) {
    ulonglong2 w0 = wp[4*k+0], w1 = wp[4*k+1], w2 = wp[4*k+2], w3 = wp[4*k+3];
    ulonglong2 h0 = hp[4*k+0], h1 = hp[4*k+1], h2 = hp[4*k+2], h3 = hp[4*k+3];
    ffma2(acc[0], w0.x, h0.x); ffma2(acc[1], w0.y, h0.y);
    ffma2(acc[2], w1.x, h1.x); ffma2(acc[3], w1.y, h1.y);
    ffma2(acc[4], w2.x, h2.x); ffma2(acc[5], w2.y, h2.y);
    ffma2(acc[6], w3.x, h3.x); ffma2(acc[7], w3.y, h3.y);
}

__device__ __forceinline__ float acc8_sum(const ull* acc) {
    float2 f0 = unpack2(acc[0]), f1 = unpack2(acc[1]), f2 = unpack2(acc[2]), f3 = unpack2(acc[3]);
    float2 f4 = unpack2(acc[4]), f5 = unpack2(acc[5]), f6 = unpack2(acc[6]), f7 = unpack2(acc[7]);
    float s0 = (f0.x + f0.y) + (f1.x + f1.y);
    float s1 = (f2.x + f2.y) + (f3.x + f3.y);
    float s2 = (f4.x + f4.y) + (f5.x + f5.y);
    float s3 = (f6.x + f6.y) + (f7.x + f7.y);
    return (s0 + s1) + (s2 + s3);
}

// ---------------- kernel 1: projection GEMM ----------------
// pre[t][b][n] = x[b,t,:] . Wx[n,:] + bias[n],  Wx row n = W[n][512..1023]
__global__ void __launch_bounds__(256) gemm_pre(const float* __restrict__ x,
                                                const float* __restrict__ W_ru,
                                                const float* __restrict__ W_c,
                                                const float* __restrict__ b_ru,
                                                const float* __restrict__ b_c) {
    __shared__ float As[2][64 * 36];
    __shared__ float Bs[2][32 * 64];
    const int tid = threadIdx.x;
    const int n0 = blockIdx.x * 64;
    const int m0 = blockIdx.y * 64;

    const float* Wsrc = (n0 < 1024) ? (W_ru + (size_t)n0 * 1024 + 512)
                                    : (W_c + (size_t)(n0 - 1024) * 1024 + 512);

    const int arow = tid >> 3, ac = (tid & 7) * 4;
    const float* Ap0 = x + (size_t)(m0 + arow) * 512 + ac;
    const int bn = tid & 63, bk = (tid >> 6) * 4;
    const float* Bp0 = Wsrc + (size_t)bn * 1024 + bk;

    const int tx = tid & 15, ty = tid >> 4;

    ull acc[4][2];
#pragma unroll
    for (int i = 0; i < 4; i++) { acc[i][0] = 0ull; acc[i][1] = 0ull; }

    float4 ra0 = *(const float4*)(Ap0);
    float4 ra1 = *(const float4*)(Ap0 + 32 * 512);
    float4 rb0 = *(const float4*)(Bp0);
    float4 rb1 = *(const float4*)(Bp0 + 16);

    *(float4*)&As[0][arow * 36 + ac] = ra0;
    *(float4*)&As[0][(arow + 32) * 36 + ac] = ra1;
    Bs[0][(bk + 0) * 64 + bn] = rb0.x; Bs[0][(bk + 1) * 64 + bn] = rb0.y;
    Bs[0][(bk + 2) * 64 + bn] = rb0.z; Bs[0][(bk + 3) * 64 + bn] = rb0.w;
    Bs[0][(bk + 16) * 64 + bn] = rb1.x; Bs[0][(bk + 17) * 64 + bn] = rb1.y;
    Bs[0][(bk + 18) * 64 + bn] = rb1.z; Bs[0][(bk + 19) * 64 + bn] = rb1.w;
    __syncthreads();

    for (int kt = 0; kt < 16; kt++) {
        const int cur = kt & 1;
        if (kt < 15) {
            const float* ap = Ap0 + (kt + 1) * 32;
            ra0 = *(const float4*)(ap);
            ra1 = *(const float4*)(ap + 32 * 512);
            const float* bp = Bp0 + (kt + 1) * 32;
            rb0 = *(const float4*)(bp);
            rb1 = *(const float4*)(bp + 16);
        }
        const float* Arow = &As[cur][ty * 4 * 36];
        const float* Bbase = &Bs[cur][0];
#pragma unroll
        for (int kk = 0; kk < 32; kk++) {
            float av0 = Arow[kk], av1 = Arow[36 + kk], av2 = Arow[72 + kk], av3 = Arow[108 + kk];
            const ull* Bq = (const ull*)(Bbase + kk * 64);
            ull b0 = Bq[tx * 2], b1 = Bq[tx * 2 + 1];
            ull s0 = splat2(av0), s1 = splat2(av1), s2 = splat2(av2), s3 = splat2(av3);
            ffma2(acc[0][0], s0, b0); ffma2(acc[0][1], s0, b1);
            ffma2(acc[1][0], s1, b0); ffma2(acc[1][1], s1, b1);
            ffma2(acc[2][0], s2, b0); ffma2(acc[2][1], s2, b1);
            ffma2(acc[3][0], s3, b0); ffma2(acc[3][1], s3, b1);
        }
        if (kt < 15) {
            const int nb = (kt + 1) & 1;
            *(float4*)&As[nb][arow * 36 + ac] = ra0;
            *(float4*)&As[nb][(arow + 32) * 36 + ac] = ra1;
            Bs[nb][(bk + 0) * 64 + bn] = rb0.x; Bs[nb][(bk + 1) * 64 + bn] = rb0.y;
            Bs[nb][(bk + 2) * 64 + bn] = rb0.z; Bs[nb][(bk + 3) * 64 + bn] = rb0.w;
            Bs[nb][(bk + 16) * 64 + bn] = rb1.x; Bs[nb][(bk + 17) * 64 + bn] = rb1.y;
            Bs[nb][(bk + 18) * 64 + bn] = rb1.z; Bs[nb][(bk + 19) * 64 + bn] = rb1.w;
        }
        __syncthreads();
    }

    const float* bias = (n0 < 1024) ? (b_ru + n0) : (b_c + (n0 - 1024));
    const float4 bv = *(const float4*)&bias[tx * 4];
#pragma unroll
    for (int i = 0; i < 4; i++) {
        int m = m0 + ty * 4 + i;
        int bb = m >> 10, tt = m & 1023;
        float2 f0 = unpack2(acc[i][0]);
        float2 f1 = unpack2(acc[i][1]);
        float4 o = make_float4(f0.x + bv.x, f0.y + bv.y, f1.x + bv.z, f1.y + bv.w);
        *(float4*)&g_pre[((size_t)tt * 32 + bb) * 1536 + n0 + tx * 4] = o;
    }
}

// ---------------- group barrier: st.release signal + acquire poll ----------------
__device__ __forceinline__ void barrier_sw(unsigned* flags, int c, unsigned target) {
    __syncthreads();
    if (threadIdx.x == 0) {
        asm volatile("st.release.gpu.u32 [%0], %1;" :: "l"(flags + c), "r"(target) : "memory");
    }
    if (threadIdx.x < CPG) {
        unsigned v;
        const unsigned* fp = flags + threadIdx.x;
        do {
            asm volatile("ld.acquire.gpu.u32 %0, [%1];" : "=r"(v) : "l"(fp) : "memory");
        } while ((int)(v - target) < 0);
    }
    __syncthreads();
}

// ---------------- kernel 2: persistent recurrent scan ----------------
// 128 CTAs = 8 groups x 16 CTAs, 256 threads, ~210KB smem (1 CTA/SM, all resident).
__global__ void __launch_bounds__(256, 1) scan_kernel(const float* __restrict__ W_ru,
                                                      const float* __restrict__ W_c,
                                                      const float* __restrict__ init_h,
                                                      float* __restrict__ out,
                                                      int has_last) {
    extern __shared__ float sm[];
    float* sWg = sm;                      // 64 x ROWP  (Wh_ru rows)
    float* sWc = sWg + 64 * ROWP;         // 32 x ROWP  (Wh_c rows)
    float* sh  = sWc + 32 * ROWP;         // 4 x ROWP
    float* srh = sh + 4 * ROWP;           // 4 x ROWP
    __shared__ unsigned sBase;

    const int tid = threadIdx.x;
    const int grp = blockIdx.x >> 4;
    const int c   = blockIdx.x & 15;
    unsigned* flags = &g_flag[grp * CPG];

    // own-flag base (only this CTA ever writes flag c; all group flags equal at entry)
    if (tid == 0) sBase = flags[c];

    // --- load recurrent weights (cols 0..511 of W rows) into smem ---
    {
        const int gbase = c * 64;
        for (int i = tid; i < 64 * 128; i += 256) {
            int r = i >> 7, q = (i & 127) * 4;
            float4 v = *(const float4*)(W_ru + (size_t)(gbase + r) * 1024 + q);
            *(float4*)(sWg + r * ROWP + q) = v;
        }
        const int nbase = c * 32;
        for (int i = tid; i < 32 * 128; i += 256) {
            int r = i >> 7, q = (i & 127) * 4;
            float4 v = *(const float4*)(W_c + (size_t)(nbase + r) * 1024 + q);
            *(float4*)(sWc + r * ROWP + q) = v;
        }
    }
    // --- stage initial h directly from input ---
    for (int i = tid; i < 4 * 128; i += 256) {
        int b = i >> 7, q = (i & 127) * 4;
        float4 v = *(const float4*)(init_h + (size_t)(grp * 4 + b) * 512 + q);
        *(float4*)(sh + b * ROWP + q) = v;
    }
    __syncthreads();
    const unsigned base = sBase;

    // phase-1 thread mapping: one (gate row, batch) per thread (warp = 8 rows x 4 b)
    const int gl  = tid >> 2;             // 0..63
    const int bl  = tid & 3;
    const int ggl = c * 64 + gl;          // global gate row 0..1023
    const int gb  = grp * 4 + bl;         // global batch
    const ulonglong2* wg_p = (const ulonglong2*)(sWg + gl * ROWP);
    const ulonglong2* sh_p = (const ulonglong2*)(sh + bl * ROWP);

    // phase-2 thread mapping: 2 threads per (cand row, batch)
    const int d    = tid >> 1;
    const int half = tid & 1;
    const int nl   = d >> 2;              // 0..31
    const int bl2  = d & 3;
    const int n    = c * 32 + nl;
    const int gb2  = grp * 4 + bl2;
    const ulonglong2* wc_p  = (const ulonglong2*)(sWc + nl * ROWP + half * 256);

    const bool is_r = (ggl < 512);
    float* rz_dst = is_r ? (g_rh + (size_t)gb * 512 + ggl)
                         : (g_z + (size_t)gb * 512 + (ggl - 512));

    float xg = __ldg(&g_pre[((size_t)0 * 32 + gb) * 1536 + ggl]);

    for (int t = 0; t < Lv; t++) {
        // ---- phase 1: gates ----
        float xc = __ldg(&g_pre[((size_t)t * 32 + gb2) * 1536 + 1024 + n]);  // prefetch phase-2 input
        ull a[8];
#pragma unroll
        for (int i = 0; i < 8; i++) a[i] = 0ull;
#pragma unroll
        for (int k = 0; k < 32; k++) dot16(wg_p, sh_p, k, a);
        float pre = acc8_sum(a) + xg;
        float gate = fast_sigmoid(pre);
        float val = is_r ? (gate * sh[bl * ROWP + ggl]) : gate;
        __stcg(rz_dst, val);

        barrier_sw(flags, c, base + 2u * t + 1u);

        // ---- stage rh ----
        for (int i = tid; i < 512; i += 256) {
            int b = i >> 7, q = (i & 127) * 4;
            float4 v = __ldcg((const float4*)(g_rh + (size_t)(grp * 4 + b) * 512 + q));
            *(float4*)(srh + b * ROWP + q) = v;
        }
        float zv = __ldcg(&g_z[(size_t)gb2 * 512 + n]);
        __syncthreads();

        // ---- phase 2: candidate + blend ----
        const ulonglong2* srh_p = (const ulonglong2*)(srh + bl2 * ROWP + half * 256);
        ull cacc[8];
#pragma unroll
        for (int i = 0; i < 8; i++) cacc[i] = 0ull;
#pragma unroll
        for (int k = 0; k < 16; k++) dot16(wc_p, srh_p, k, cacc);
        float tot = acc8_sum(cacc);
        tot += __shfl_xor_sync(0xffffffffu, tot, 1);

        // prefetch next step's gate input before the barrier
        if (t < Lv - 1) xg = __ldg(&g_pre[((size_t)(t + 1) * 32 + gb) * 1536 + ggl]);

        if (half == 0) {
            float cand = fast_tanh(tot + xc);
            float hold = sh[bl2 * ROWP + n];
            float hnew = hold + zv * (cand - hold);       // (1-z)*h + z*cand
            __stcg(&g_h[(size_t)gb2 * 512 + n], hnew);
            out[(size_t)gb2 * ((size_t)Lv * 512) + (size_t)t * 512 + n] = hnew;
            if (has_last && t == Lv - 1)
                out[(size_t)Bv * Lv * 512 + (size_t)gb2 * 512 + n] = hnew;
        }

        barrier_sw(flags, c, base + 2u * t + 2u);

        // ---- restage h for next step ----
        if (t < Lv - 1) {
            for (int i = tid; i < 512; i += 256) {
                int b = i >> 7, q = (i & 127) * 4;
                float4 v = __ldcg((const float4*)(g_h + (size_t)(grp * 4 + b) * 512 + q));
                *(float4*)(sh + b * ROWP + q) = v;
            }
            __syncthreads();
        }
    }
}

// ---------------- launch ----------------
extern "C" void kernel_launch(void* const* d_in, const int* in_sizes, int n_in,
                              void* d_out, int out_size) {
    const float* x      = (const float*)d_in[0];
    const float* init_h = (const float*)d_in[1];
    const float* W_ru   = (const float*)d_in[2];
    const float* b_ru   = (const float*)d_in[3];
    const float* W_c    = (const float*)d_in[4];
    const float* b_c    = (const float*)d_in[5];
    float* out = (float*)d_out;

    const int smem_bytes = (64 * ROWP + 32 * ROWP + 8 * ROWP) * 4;  // 214,656 B
    cudaFuncSetAttribute(scan_kernel, cudaFuncAttributeMaxDynamicSharedMemorySize, smem_bytes);

    int has_last = (out_size >= Bv * Lv * Hv + Bv * Hv) ? 1 : 0;

    gemm_pre<<<dim3(24, 512), 256>>>(x, W_ru, W_c, b_ru, b_c);
    scan_kernel<<<NGROUP * CPG, 256, smem_bytes>>>(W_ru, W_c, init_h, out, has_last);
}